// round 15
// baseline (speedup 1.0000x reference)
#include <cuda_runtime.h>
#include <cuda_fp16.h>
#include <math.h>
#include <stdint.h>

// Problem constants
#define Bn  2
#define Sn  2048
#define Dn  1024
#define Hn  16
#define HDn 64
#define Mn  (Bn * Sn)   // 4096

// Scratch (static device allocations — no cudaMalloc anywhere)
__device__ __half g_xh[(size_t)Mn * Dn];           // 8 MB
__device__ __half g_Wh[4][(size_t)Dn * Dn];        // 8 MB  Wq,Wk,Wv,Wo fp16
__device__ __half g_Qh[(size_t)Mn * Dn];           // 8 MB
__device__ __half g_Kh[(size_t)Mn * Dn];           // 8 MB
__device__ __half g_Vh[(size_t)Mn * Dn];           // 8 MB
__device__ __half g_Vt[(size_t)Bn * Dn * Sn];      // 8 MB  V transposed [b][d][tok]
__device__ __half g_SP[(size_t)Bn * Hn * Sn * Sn]; // 256 MB fp16 scores -> probs (in place)
__device__ __half g_AOh[(size_t)Mn * Dn];          // 8 MB

// ---------------------------------------------------------------------------
// PTX helpers
// ---------------------------------------------------------------------------
__device__ __forceinline__ uint32_t smem_u32(const void* p) {
    return (uint32_t)__cvta_generic_to_shared(p);
}
__device__ __forceinline__ void cp16(uint32_t dst, const void* src) {
    asm volatile("cp.async.cg.shared.global [%0], [%1], 16;\n" :: "r"(dst), "l"(src));
}
__device__ __forceinline__ void cp_commit() { asm volatile("cp.async.commit_group;\n"); }
__device__ __forceinline__ void cp_wait0()  { asm volatile("cp.async.wait_group 0;\n"); }

__device__ __forceinline__ void ldsm4(uint32_t& r0, uint32_t& r1, uint32_t& r2, uint32_t& r3,
                                      uint32_t addr) {
    asm volatile("ldmatrix.sync.aligned.m8n8.x4.shared.b16 {%0,%1,%2,%3}, [%4];\n"
                 : "=r"(r0), "=r"(r1), "=r"(r2), "=r"(r3) : "r"(addr));
}
__device__ __forceinline__ void mma16816(float* c,
                                         uint32_t a0, uint32_t a1, uint32_t a2, uint32_t a3,
                                         uint32_t b0, uint32_t b1) {
    asm volatile(
        "mma.sync.aligned.m16n8k16.row.col.f32.f16.f16.f32 "
        "{%0,%1,%2,%3},{%4,%5,%6,%7},{%8,%9},{%0,%1,%2,%3};\n"
        : "+f"(c[0]), "+f"(c[1]), "+f"(c[2]), "+f"(c[3])
        : "r"(a0), "r"(a1), "r"(a2), "r"(a3), "r"(b0), "r"(b1));
}

// 64B-row swizzle (row stride 64B = 4 chunks of 16B)
__device__ __forceinline__ uint32_t sw_off(int row, int chunk) {
    return ((uint32_t)row << 6) + ((uint32_t)((chunk ^ (row & 3) ^ ((row >> 2) & 1))) << 4);
}
// 128B-row swizzle (8 chunks of 16B per row): phys = c ^ (row & 7)
__device__ __forceinline__ uint32_t sw128(int row, int chunk) {
    return ((uint32_t)row << 7) + ((uint32_t)((chunk ^ (row & 7))) << 4);
}

// ---------------------------------------------------------------------------
// fp16 NT GEMM core (validated round-7 2-stage): C = scale*A*W^T (+bias)
// Block 128x128, BK=32, 256 thr, warp tile 32x64, cp.async double-buffered.
// ---------------------------------------------------------------------------
template <bool OUT_HALF>
__device__ __forceinline__ void gemm_nt_f16(
    const __half* __restrict__ A, int lda,
    const __half* __restrict__ W, int ldw,
    const float* __restrict__ bias,
    void* __restrict__ Cv, int ldc,
    int K, float scale, int bm, int bn)
{
    __shared__ __align__(16) char As[2][8192];
    __shared__ __align__(16) char Ws[2][8192];

    const int tid  = threadIdx.x;
    const int lane = tid & 31;
    const int warp = tid >> 5;
    const int grp  = lane >> 2;
    const int tig  = lane & 3;
    const int wm   = (warp & 3) * 32;
    const int wn   = (warp >> 2) * 64;
    const int lrow = tid >> 1;
    const int lc2  = (tid & 1) * 2;

    uint32_t asb[2] = { smem_u32(As[0]), smem_u32(As[1]) };
    uint32_t wsb[2] = { smem_u32(Ws[0]), smem_u32(Ws[1]) };

    const __half* Ag = A + (size_t)(bm + lrow) * lda;
    const __half* Wg = W + (size_t)(bn + lrow) * ldw;

    float acc[2][8][4] = {};

    const int nIter = K >> 5;
    cp16(asb[0] + sw_off(lrow, lc2),     Ag + lc2 * 8);
    cp16(asb[0] + sw_off(lrow, lc2 + 1), Ag + lc2 * 8 + 8);
    cp16(wsb[0] + sw_off(lrow, lc2),     Wg + lc2 * 8);
    cp16(wsb[0] + sw_off(lrow, lc2 + 1), Wg + lc2 * 8 + 8);
    cp_commit();

    for (int it = 0; it < nIter; ++it) {
        const int buf = it & 1;
        cp_wait0();
        __syncthreads();
        if (it + 1 < nIter) {
            const int k0 = (it + 1) << 5;
            cp16(asb[buf ^ 1] + sw_off(lrow, lc2),     Ag + k0 + lc2 * 8);
            cp16(asb[buf ^ 1] + sw_off(lrow, lc2 + 1), Ag + k0 + lc2 * 8 + 8);
            cp16(wsb[buf ^ 1] + sw_off(lrow, lc2),     Wg + k0 + lc2 * 8);
            cp16(wsb[buf ^ 1] + sw_off(lrow, lc2 + 1), Wg + k0 + lc2 * 8 + 8);
            cp_commit();
        }
        #pragma unroll
        for (int ks = 0; ks < 2; ++ks) {
            const int frow = (lane & 7) + ((lane >> 3) & 1) * 8;
            const int fch  = ks * 2 + (lane >> 4);
            uint32_t a[2][4];
            #pragma unroll
            for (int mi = 0; mi < 2; ++mi)
                ldsm4(a[mi][0], a[mi][1], a[mi][2], a[mi][3],
                      asb[buf] + sw_off(wm + mi * 16 + frow, fch));
            uint32_t b[8][2];
            #pragma unroll
            for (int nj = 0; nj < 4; ++nj) {
                uint32_t r0, r1, r2, r3;
                ldsm4(r0, r1, r2, r3, wsb[buf] + sw_off(wn + nj * 16 + frow, fch));
                b[nj * 2][0] = r0;  b[nj * 2][1] = r2;
                b[nj * 2 + 1][0] = r1;  b[nj * 2 + 1][1] = r3;
            }
            #pragma unroll
            for (int mi = 0; mi < 2; ++mi)
                #pragma unroll
                for (int ni = 0; ni < 8; ++ni)
                    mma16816(acc[mi][ni], a[mi][0], a[mi][1], a[mi][2], a[mi][3],
                             b[ni][0], b[ni][1]);
        }
    }

    #pragma unroll
    for (int mi = 0; mi < 2; ++mi) {
        const int r0 = bm + wm + mi * 16 + grp;
        #pragma unroll
        for (int ni = 0; ni < 8; ++ni) {
            const int c0 = bn + wn + ni * 8 + 2 * tig;
            float bx = 0.f, by = 0.f;
            if (bias) { bx = bias[c0]; by = bias[c0 + 1]; }
            const float x0 = acc[mi][ni][0] * scale + bx;
            const float y0 = acc[mi][ni][1] * scale + by;
            const float x1 = acc[mi][ni][2] * scale + bx;
            const float y1 = acc[mi][ni][3] * scale + by;
            if (OUT_HALF) {
                __half* C = (__half*)Cv;
                *(__half2*)&C[(size_t)r0 * ldc + c0]       = __floats2half2_rn(x0, y0);
                *(__half2*)&C[(size_t)(r0 + 8) * ldc + c0] = __floats2half2_rn(x1, y1);
            } else {
                float* C = (float*)Cv;
                *(float2*)&C[(size_t)r0 * ldc + c0]       = make_float2(x0, y0);
                *(float2*)&C[(size_t)(r0 + 8) * ldc + c0] = make_float2(x1, y1);
            }
        }
    }
}

// Fused QKV projection: blockIdx.z selects {Q,K,V}
__global__ void __launch_bounds__(256) qkv_h(
    const __half* __restrict__ xh,
    const float* __restrict__ bq, const float* __restrict__ bk,
    const float* __restrict__ bv)
{
    const int which = blockIdx.z;
    const __half* W = g_Wh[which];
    const float* bias = (which == 0) ? bq : (which == 1) ? bk : bv;
    __half* C = (which == 0) ? g_Qh : (which == 1) ? g_Kh : g_Vh;
    gemm_nt_f16<true>(xh, Dn, W, Dn, bias, C, Dn, Dn, 1.0f,
                      blockIdx.y * 128, blockIdx.x * 128);
}

// Final projection: out fp32
__global__ void __launch_bounds__(256) proj_f(
    const __half* __restrict__ A, const __half* __restrict__ W,
    const float* __restrict__ bias, float* __restrict__ C)
{
    gemm_nt_f16<false>(A, Dn, W, Dn, bias, C, Dn, Dn, 1.0f,
                       blockIdx.y * 128, blockIdx.x * 128);
}

// ---------------------------------------------------------------------------
// Scores, K=64, MULTI-K-TILE (8 tiles): block keeps Q tile (128 rows) resident
// and processes 8 consecutive 128-col K tiles with double-buffered K prefetch;
// the prefetch of K_{j+1} overlaps MMA + staged epilogue of tile j.
// smem (dynamic, 82KB): Q 16K | K[2] 32K | staging 34K (stride 272B).
// S[q,k] = 0.125 * dot(Q_h[q,:], K_h[k,:]); fp16 out.
// grid (Sn/1024, Sn/128, Bn*Hn), 256 thr.
// ---------------------------------------------------------------------------
#define SC_SMEM 83968

__global__ void __launch_bounds__(256) scores_k64m()
{
    extern __shared__ __align__(16) char sbuf[];
    uint32_t qsb = smem_u32(sbuf);
    uint32_t ksb[2] = { qsb + 16384, qsb + 32768 };
    char* stage = sbuf + 49152;

    const int zb = blockIdx.z;
    const int b  = zb >> 4;
    const int h  = zb & 15;
    const __half* A = g_Qh + (size_t)b * Sn * Dn + h * HDn;
    const __half* W = g_Kh + (size_t)b * Sn * Dn + h * HDn;
    __half* C = g_SP + (size_t)zb * Sn * Sn;

    const int bm      = blockIdx.y * 128;
    const int bn_base = blockIdx.x * 1024;
    const int tid  = threadIdx.x;
    const int lane = tid & 31;
    const int warp = tid >> 5;
    const int grp  = lane >> 2;
    const int tig  = lane & 3;
    const int wm   = (warp & 3) * 32;
    const int wn   = (warp >> 2) * 64;
    const int lrow = tid >> 1;          // 0..127
    const int lc4  = (tid & 1) * 4;     // chunks 0..3 or 4..7

    // load Q (once) + K tile 0
    {
        const __half* Ag = A + (size_t)(bm + lrow) * Dn;
        const __half* Wg = W + (size_t)(bn_base + lrow) * Dn;
        #pragma unroll
        for (int i = 0; i < 4; ++i) {
            cp16(qsb    + sw128(lrow, lc4 + i), Ag + (lc4 + i) * 8);
            cp16(ksb[0] + sw128(lrow, lc4 + i), Wg + (lc4 + i) * 8);
        }
        cp_commit();
    }

    const int frow = (lane & 7) + ((lane >> 3) & 1) * 8;
    const int fsel = lane >> 4;
    const int ct = tid & 15;        // store: 16B chunk within row
    const int rb = tid >> 4;        // store: base row 0..15

    #pragma unroll
    for (int j = 0; j < 8; ++j) {
        cp_wait0();          // K_j (and Q at j=0) complete
        __syncthreads();

        // prefetch K_{j+1} into the other buffer; overlaps MMA + stores below
        if (j + 1 < 8) {
            const __half* Wg = W + (size_t)(bn_base + (j + 1) * 128 + lrow) * Dn;
            #pragma unroll
            for (int i = 0; i < 4; ++i)
                cp16(ksb[(j + 1) & 1] + sw128(lrow, lc4 + i), Wg + (lc4 + i) * 8);
            cp_commit();
        }

        float acc[2][8][4] = {};
        const uint32_t kb = ksb[j & 1];
        #pragma unroll
        for (int ks = 0; ks < 4; ++ks) {
            const int fch = 2 * ks + fsel;
            uint32_t a[2][4];
            #pragma unroll
            for (int mi = 0; mi < 2; ++mi)
                ldsm4(a[mi][0], a[mi][1], a[mi][2], a[mi][3],
                      qsb + sw128(wm + mi * 16 + frow, fch));
            uint32_t bfr[8][2];
            #pragma unroll
            for (int nj = 0; nj < 4; ++nj) {
                uint32_t r0, r1, r2, r3;
                ldsm4(r0, r1, r2, r3, kb + sw128(wn + nj * 16 + frow, fch));
                bfr[nj * 2][0] = r0;  bfr[nj * 2][1] = r2;
                bfr[nj * 2 + 1][0] = r1;  bfr[nj * 2 + 1][1] = r3;
            }
            #pragma unroll
            for (int mi = 0; mi < 2; ++mi)
                #pragma unroll
                for (int ni = 0; ni < 8; ++ni)
                    mma16816(acc[mi][ni], a[mi][0], a[mi][1], a[mi][2], a[mi][3],
                             bfr[ni][0], bfr[ni][1]);
        }

        // staged epilogue: fragments -> staging (stride 272, conflict-free)
        #pragma unroll
        for (int mi = 0; mi < 2; ++mi) {
            const int r0 = wm + mi * 16 + grp;
            #pragma unroll
            for (int ni = 0; ni < 8; ++ni) {
                const int c0 = wn + ni * 8 + 2 * tig;
                *(__half2*)(stage + (size_t)r0 * 272 + c0 * 2) =
                    __floats2half2_rn(acc[mi][ni][0] * 0.125f, acc[mi][ni][1] * 0.125f);
                *(__half2*)(stage + (size_t)(r0 + 8) * 272 + c0 * 2) =
                    __floats2half2_rn(acc[mi][ni][2] * 0.125f, acc[mi][ni][3] * 0.125f);
            }
        }
        __syncthreads();

        // coalesced store: warp covers 2 full 256B rows per instruction
        const int bn = bn_base + j * 128;
        #pragma unroll
        for (int i = 0; i < 8; ++i) {
            const int row = rb + 16 * i;
            uint4 v = *(uint4*)(stage + (size_t)row * 272 + ct * 16);
            *(uint4*)&C[(size_t)(bm + row) * Sn + bn + ct * 8] = v;
        }
        __syncthreads();   // staging reads done before next iter's stage writes
    }
}

// ---------------------------------------------------------------------------
// Softmax over HEAD axis (axis=1, faithful), IN PLACE, 8 k-positions/thread
// (uint4 loads/stores). fp32 value regs -> numerics identical to 4-wide.
// grid: Bn*Sn*Sn/8/256 blocks.
// ---------------------------------------------------------------------------
__global__ void __launch_bounds__(256) softmax_h16w8()
{
    const size_t SS = (size_t)Sn * Sn;
    const size_t idx = (size_t)blockIdx.x * 256 + threadIdx.x;   // < Bn*SS/8
    const size_t b    = idx / (SS / 8);
    const size_t rem8 = idx % (SS / 8);
    __half* base = g_SP + b * Hn * SS + rem8 * 8;

    float v[Hn][8];
    float mx[8];
    #pragma unroll
    for (int j = 0; j < 8; ++j) mx[j] = -1e30f;

    #pragma unroll
    for (int h = 0; h < Hn; ++h) {
        uint4 u = *(uint4*)&base[(size_t)h * SS];
        float2 p0 = __half22float2(*(__half2*)&u.x);
        float2 p1 = __half22float2(*(__half2*)&u.y);
        float2 p2 = __half22float2(*(__half2*)&u.z);
        float2 p3 = __half22float2(*(__half2*)&u.w);
        v[h][0] = p0.x; v[h][1] = p0.y; v[h][2] = p1.x; v[h][3] = p1.y;
        v[h][4] = p2.x; v[h][5] = p2.y; v[h][6] = p3.x; v[h][7] = p3.y;
        #pragma unroll
        for (int j = 0; j < 8; ++j) mx[j] = fmaxf(mx[j], v[h][j]);
    }
    float sum[8];
    #pragma unroll
    for (int j = 0; j < 8; ++j) sum[j] = 0.f;
    #pragma unroll
    for (int h = 0; h < Hn; ++h) {
        #pragma unroll
        for (int j = 0; j < 8; ++j) {
            v[h][j] = __expf(v[h][j] - mx[j]);
            sum[j] += v[h][j];
        }
    }
    float inv[8];
    #pragma unroll
    for (int j = 0; j < 8; ++j) inv[j] = 1.f / sum[j];
    #pragma unroll
    for (int h = 0; h < Hn; ++h) {
        __half2 h0 = __floats2half2_rn(v[h][0] * inv[0], v[h][1] * inv[1]);
        __half2 h1 = __floats2half2_rn(v[h][2] * inv[2], v[h][3] * inv[3]);
        __half2 h2 = __floats2half2_rn(v[h][4] * inv[4], v[h][5] * inv[5]);
        __half2 h3 = __floats2half2_rn(v[h][6] * inv[6], v[h][7] * inv[7]);
        uint4 u;
        u.x = *(uint32_t*)&h0;  u.y = *(uint32_t*)&h1;
        u.z = *(uint32_t*)&h2;  u.w = *(uint32_t*)&h3;
        *(uint4*)&base[(size_t)h * SS] = u;
    }
}

// ---------------------------------------------------------------------------
// Transpose Vh[b*S + tok][d] -> Vt[b][d][tok] (fp16), 64x64 tiles
// ---------------------------------------------------------------------------
__global__ void __launch_bounds__(256) transpose_v()
{
    __shared__ __half ts[64][72];
    const int t0 = blockIdx.x * 64;
    const int d0 = blockIdx.y * 64;
    const int b  = blockIdx.z;
    const int tid = threadIdx.x;

    const __half* src = g_Vh + ((size_t)b * Sn + t0) * Dn + d0;
    const int r = tid >> 2, c2 = (tid & 3) * 2;
    *(uint4*)&ts[r][c2 * 8]     = *(const uint4*)(src + (size_t)r * Dn + c2 * 8);
    *(uint4*)&ts[r][c2 * 8 + 8] = *(const uint4*)(src + (size_t)r * Dn + c2 * 8 + 8);
    __syncthreads();

    const int dl = tid >> 2, seg = tid & 3;
    __half tmp[16];
    #pragma unroll
    for (int j = 0; j < 16; ++j) tmp[j] = ts[seg * 16 + j][dl];
    __half* dst = g_Vt + ((size_t)b * Dn + d0 + dl) * Sn + t0 + seg * 16;
    *(uint4*)dst       = *(uint4*)tmp;
    *(uint4*)(dst + 8) = *(uint4*)(tmp + 8);
}

// ---------------------------------------------------------------------------
// AV, 256q blocks (512 thr, 16 warps on m), BK=32 2-stage:
// per (b,h): O[q,d] = sum_k P_h[q,k] * Vt_h[d,k].
// smem: 2 x (16KB P + 4KB V) = 40KB. grid (S/256, 1, B*H) = 256 blocks.
// ---------------------------------------------------------------------------
__global__ void __launch_bounds__(512) av_h2()
{
    __shared__ __align__(16) char Ps[2][16384];   // 256 rows x 64 B
    __shared__ __align__(16) char Vs[2][4096];    // 64 rows x 64 B

    const int zb = blockIdx.z;
    const int b  = zb >> 4;
    const int h  = zb & 15;
    const __half* P  = g_SP + (size_t)zb * Sn * Sn;
    const __half* Vt = g_Vt + ((size_t)b * Dn + h * HDn) * Sn;
    __half* C = g_AOh + (size_t)b * Sn * Dn + h * HDn;

    const int tid  = threadIdx.x;
    const int lane = tid & 31;
    const int warp = tid >> 5;          // 0..15
    const int grp  = lane >> 2;
    const int tig  = lane & 3;
    const int bm   = blockIdx.x * 256;
    const int wm   = warp * 16;         // 0..240
    const int prow = tid >> 1;          // 0..255
    const int pc2  = (tid & 1) * 2;     // chunks 0-1 or 2-3
    const int vrow = (tid & 255) >> 2;  // 0..63
    const int vc   = tid & 3;           // 0..3
    const bool vldr = tid < 256;

    uint32_t psb[2] = { smem_u32(Ps[0]), smem_u32(Ps[1]) };
    uint32_t vsb[2] = { smem_u32(Vs[0]), smem_u32(Vs[1]) };

    const __half* Pg = P  + (size_t)(bm + prow) * Sn;
    const __half* Vg = Vt + (size_t)vrow * Sn;

    float acc[8][4] = {};

    cp16(psb[0] + sw_off(prow, pc2),     Pg + pc2 * 8);
    cp16(psb[0] + sw_off(prow, pc2 + 1), Pg + pc2 * 8 + 8);
    if (vldr) cp16(vsb[0] + sw_off(vrow, vc), Vg + vc * 8);
    cp_commit();

    const int nIter = Sn >> 5;   // 64
    for (int it = 0; it < nIter; ++it) {
        const int buf = it & 1;
        cp_wait0();
        __syncthreads();
        if (it + 1 < nIter) {
            const int k0 = (it + 1) << 5;
            cp16(psb[buf ^ 1] + sw_off(prow, pc2),     Pg + k0 + pc2 * 8);
            cp16(psb[buf ^ 1] + sw_off(prow, pc2 + 1), Pg + k0 + pc2 * 8 + 8);
            if (vldr) cp16(vsb[buf ^ 1] + sw_off(vrow, vc), Vg + k0 + vc * 8);
            cp_commit();
        }
        #pragma unroll
        for (int ks = 0; ks < 2; ++ks) {
            const int frow = (lane & 7) + ((lane >> 3) & 1) * 8;
            const int fch  = ks * 2 + (lane >> 4);
            uint32_t a[4];
            ldsm4(a[0], a[1], a[2], a[3], psb[buf] + sw_off(wm + frow, fch));
            uint32_t bfr[8][2];
            #pragma unroll
            for (int nj = 0; nj < 4; ++nj) {
                uint32_t r0, r1, r2, r3;
                ldsm4(r0, r1, r2, r3, vsb[buf] + sw_off(nj * 16 + frow, fch));
                bfr[nj * 2][0] = r0;  bfr[nj * 2][1] = r2;
                bfr[nj * 2 + 1][0] = r1;  bfr[nj * 2 + 1][1] = r3;
            }
            #pragma unroll
            for (int ni = 0; ni < 8; ++ni)
                mma16816(acc[ni], a[0], a[1], a[2], a[3], bfr[ni][0], bfr[ni][1]);
        }
    }

    const int r0 = bm + wm + grp;
    #pragma unroll
    for (int ni = 0; ni < 8; ++ni) {
        const int c0 = ni * 8 + 2 * tig;
        *(__half2*)&C[(size_t)r0 * Dn + c0]       = __floats2half2_rn(acc[ni][0], acc[ni][1]);
        *(__half2*)&C[(size_t)(r0 + 8) * Dn + c0] = __floats2half2_rn(acc[ni][2], acc[ni][3]);
    }
}

// ---------------------------------------------------------------------------
// One-shot fp32 -> fp16 conversion of x + 4 weight matrices.
// ---------------------------------------------------------------------------
__global__ void __launch_bounds__(256) conv_all(
    const float* __restrict__ x,
    const float* __restrict__ Wq, const float* __restrict__ Wk,
    const float* __restrict__ Wv, const float* __restrict__ Wo)
{
    const size_t t = (size_t)blockIdx.x * 256 + threadIdx.x;
    const float* s;
    __half* d;
    size_t off;
    if (t < 524288)      { s = x;  d = g_xh;    off = t; }
    else if (t < 655360) { s = Wq; d = g_Wh[0]; off = t - 524288; }
    else if (t < 786432) { s = Wk; d = g_Wh[1]; off = t - 655360; }
    else if (t < 917504) { s = Wv; d = g_Wh[2]; off = t - 786432; }
    else                 { s = Wo; d = g_Wh[3]; off = t - 917504; }
    const size_t i = off * 8;
    float4 a = *(const float4*)(s + i);
    float4 b = *(const float4*)(s + i + 4);
    __half2 h0 = __floats2half2_rn(a.x, a.y), h1 = __floats2half2_rn(a.z, a.w);
    __half2 h2 = __floats2half2_rn(b.x, b.y), h3 = __floats2half2_rn(b.z, b.w);
    uint4 o;
    o.x = *(uint32_t*)&h0; o.y = *(uint32_t*)&h1;
    o.z = *(uint32_t*)&h2; o.w = *(uint32_t*)&h3;
    *(uint4*)(d + i) = o;
}

// ---------------------------------------------------------------------------
extern "C" void kernel_launch(void* const* d_in, const int* in_sizes, int n_in,
                              void* d_out, int out_size)
{
    const float* x  = (const float*)d_in[0];
    const float* Wq = (const float*)d_in[1];
    const float* bq = (const float*)d_in[2];
    const float* Wk = (const float*)d_in[3];
    const float* bk = (const float*)d_in[4];
    const float* Wv = (const float*)d_in[5];
    const float* bv = (const float*)d_in[6];
    const float* Wo = (const float*)d_in[7];
    const float* bo = (const float*)d_in[8];
    float* out = (float*)d_out;

    __half *xh, *Wh, *AOh;
    cudaGetSymbolAddress((void**)&xh,  g_xh);
    cudaGetSymbolAddress((void**)&Wh,  g_Wh);
    cudaGetSymbolAddress((void**)&AOh, g_AOh);

    const size_t WN = (size_t)Dn * Dn;

    // launch 0: all conversions
    conv_all<<<4096, 256>>>(x, Wq, Wk, Wv, Wo);

    // launch 1: fused QKV projections (2-stage core)
    dim3 gqkv(Dn / 128, Mn / 128, 3);
    qkv_h<<<gqkv, 256>>>(xh, bq, bk, bv);

    // launch 2: V transpose
    dim3 gtr(Sn / 64, Dn / 64, Bn);
    transpose_v<<<gtr, 256>>>();

    // launch 3: scores, K=64 multi-k-tile (8 tiles), staged epilogue (fp16 out)
    cudaFuncSetAttribute(scores_k64m,
                         cudaFuncAttributeMaxDynamicSharedMemorySize, SC_SMEM);
    dim3 gs(Sn / 1024, Sn / 128, Bn * Hn);
    scores_k64m<<<gs, 256, SC_SMEM>>>();

    // launch 4: softmax over head axis, in place (8 positions/thread, uint4)
    const size_t tot8 = (size_t)Bn * Sn * Sn / 8;
    softmax_h16w8<<<(unsigned)(tot8 / 256), 256>>>();

    // launch 5: attn @ V (256q blocks, 512 thr, BK=32 2-stage)
    dim3 gav(Sn / 256, 1, Bn * Hn);
    av_h2<<<gav, 512>>>();

    // launch 6: output projection (2-stage core)
    dim3 gproj(Dn / 128, Mn / 128);
    proj_f<<<gproj, 256>>>(AOh, Wh + 3 * WN, bo, out);
}

// round 16
// speedup vs baseline: 1.0649x; 1.0649x over previous
#include <cuda_runtime.h>
#include <cuda_fp16.h>
#include <math.h>
#include <stdint.h>

// Problem constants
#define Bn  2
#define Sn  2048
#define Dn  1024
#define Hn  16
#define HDn 64
#define Mn  (Bn * Sn)   // 4096

// Scratch (static device allocations — no cudaMalloc anywhere)
__device__ __half g_xh[(size_t)Mn * Dn];           // 8 MB
__device__ __half g_Wh[4][(size_t)Dn * Dn];        // 8 MB  Wq,Wk,Wv,Wo fp16
__device__ __half g_Qh[(size_t)Mn * Dn];           // 8 MB
__device__ __half g_Kh[(size_t)Mn * Dn];           // 8 MB
__device__ __half g_Vh[(size_t)Mn * Dn];           // 8 MB
__device__ __half g_Vt[(size_t)Bn * Dn * Sn];      // 8 MB  V transposed [b][d][tok]
__device__ __half g_SP[(size_t)Bn * Hn * Sn * Sn]; // 256 MB fp16 scores -> probs (in place)
__device__ __half g_AOh[(size_t)Mn * Dn];          // 8 MB

// ---------------------------------------------------------------------------
// PTX helpers
// ---------------------------------------------------------------------------
__device__ __forceinline__ uint32_t smem_u32(const void* p) {
    return (uint32_t)__cvta_generic_to_shared(p);
}
__device__ __forceinline__ void cp16(uint32_t dst, const void* src) {
    asm volatile("cp.async.cg.shared.global [%0], [%1], 16;\n" :: "r"(dst), "l"(src));
}
__device__ __forceinline__ void cp_commit() { asm volatile("cp.async.commit_group;\n"); }
__device__ __forceinline__ void cp_wait0()  { asm volatile("cp.async.wait_group 0;\n"); }

__device__ __forceinline__ void ldsm4(uint32_t& r0, uint32_t& r1, uint32_t& r2, uint32_t& r3,
                                      uint32_t addr) {
    asm volatile("ldmatrix.sync.aligned.m8n8.x4.shared.b16 {%0,%1,%2,%3}, [%4];\n"
                 : "=r"(r0), "=r"(r1), "=r"(r2), "=r"(r3) : "r"(addr));
}
__device__ __forceinline__ void mma16816(float* c,
                                         uint32_t a0, uint32_t a1, uint32_t a2, uint32_t a3,
                                         uint32_t b0, uint32_t b1) {
    asm volatile(
        "mma.sync.aligned.m16n8k16.row.col.f32.f16.f16.f32 "
        "{%0,%1,%2,%3},{%4,%5,%6,%7},{%8,%9},{%0,%1,%2,%3};\n"
        : "+f"(c[0]), "+f"(c[1]), "+f"(c[2]), "+f"(c[3])
        : "r"(a0), "r"(a1), "r"(a2), "r"(a3), "r"(b0), "r"(b1));
}

// 64B-row swizzle (row stride 64B = 4 chunks of 16B)
__device__ __forceinline__ uint32_t sw_off(int row, int chunk) {
    return ((uint32_t)row << 6) + ((uint32_t)((chunk ^ (row & 3) ^ ((row >> 2) & 1))) << 4);
}
// 128B-row swizzle (8 chunks of 16B per row): phys = c ^ (row & 7)
__device__ __forceinline__ uint32_t sw128(int row, int chunk) {
    return ((uint32_t)row << 7) + ((uint32_t)((chunk ^ (row & 7))) << 4);
}

// ---------------------------------------------------------------------------
// fp16 NT GEMM core (validated round-7 2-stage): C = scale*A*W^T (+bias)
// Block 128x128, BK=32, 256 thr, warp tile 32x64, cp.async double-buffered.
// ---------------------------------------------------------------------------
template <bool OUT_HALF>
__device__ __forceinline__ void gemm_nt_f16(
    const __half* __restrict__ A, int lda,
    const __half* __restrict__ W, int ldw,
    const float* __restrict__ bias,
    void* __restrict__ Cv, int ldc,
    int K, float scale, int bm, int bn)
{
    __shared__ __align__(16) char As[2][8192];
    __shared__ __align__(16) char Ws[2][8192];

    const int tid  = threadIdx.x;
    const int lane = tid & 31;
    const int warp = tid >> 5;
    const int grp  = lane >> 2;
    const int tig  = lane & 3;
    const int wm   = (warp & 3) * 32;
    const int wn   = (warp >> 2) * 64;
    const int lrow = tid >> 1;
    const int lc2  = (tid & 1) * 2;

    uint32_t asb[2] = { smem_u32(As[0]), smem_u32(As[1]) };
    uint32_t wsb[2] = { smem_u32(Ws[0]), smem_u32(Ws[1]) };

    const __half* Ag = A + (size_t)(bm + lrow) * lda;
    const __half* Wg = W + (size_t)(bn + lrow) * ldw;

    float acc[2][8][4] = {};

    const int nIter = K >> 5;
    cp16(asb[0] + sw_off(lrow, lc2),     Ag + lc2 * 8);
    cp16(asb[0] + sw_off(lrow, lc2 + 1), Ag + lc2 * 8 + 8);
    cp16(wsb[0] + sw_off(lrow, lc2),     Wg + lc2 * 8);
    cp16(wsb[0] + sw_off(lrow, lc2 + 1), Wg + lc2 * 8 + 8);
    cp_commit();

    for (int it = 0; it < nIter; ++it) {
        const int buf = it & 1;
        cp_wait0();
        __syncthreads();
        if (it + 1 < nIter) {
            const int k0 = (it + 1) << 5;
            cp16(asb[buf ^ 1] + sw_off(lrow, lc2),     Ag + k0 + lc2 * 8);
            cp16(asb[buf ^ 1] + sw_off(lrow, lc2 + 1), Ag + k0 + lc2 * 8 + 8);
            cp16(wsb[buf ^ 1] + sw_off(lrow, lc2),     Wg + k0 + lc2 * 8);
            cp16(wsb[buf ^ 1] + sw_off(lrow, lc2 + 1), Wg + k0 + lc2 * 8 + 8);
            cp_commit();
        }
        #pragma unroll
        for (int ks = 0; ks < 2; ++ks) {
            const int frow = (lane & 7) + ((lane >> 3) & 1) * 8;
            const int fch  = ks * 2 + (lane >> 4);
            uint32_t a[2][4];
            #pragma unroll
            for (int mi = 0; mi < 2; ++mi)
                ldsm4(a[mi][0], a[mi][1], a[mi][2], a[mi][3],
                      asb[buf] + sw_off(wm + mi * 16 + frow, fch));
            uint32_t b[8][2];
            #pragma unroll
            for (int nj = 0; nj < 4; ++nj) {
                uint32_t r0, r1, r2, r3;
                ldsm4(r0, r1, r2, r3, wsb[buf] + sw_off(wn + nj * 16 + frow, fch));
                b[nj * 2][0] = r0;  b[nj * 2][1] = r2;
                b[nj * 2 + 1][0] = r1;  b[nj * 2 + 1][1] = r3;
            }
            #pragma unroll
            for (int mi = 0; mi < 2; ++mi)
                #pragma unroll
                for (int ni = 0; ni < 8; ++ni)
                    mma16816(acc[mi][ni], a[mi][0], a[mi][1], a[mi][2], a[mi][3],
                             b[ni][0], b[ni][1]);
        }
    }

    #pragma unroll
    for (int mi = 0; mi < 2; ++mi) {
        const int r0 = bm + wm + mi * 16 + grp;
        #pragma unroll
        for (int ni = 0; ni < 8; ++ni) {
            const int c0 = bn + wn + ni * 8 + 2 * tig;
            float bx = 0.f, by = 0.f;
            if (bias) { bx = bias[c0]; by = bias[c0 + 1]; }
            const float x0 = acc[mi][ni][0] * scale + bx;
            const float y0 = acc[mi][ni][1] * scale + by;
            const float x1 = acc[mi][ni][2] * scale + bx;
            const float y1 = acc[mi][ni][3] * scale + by;
            if (OUT_HALF) {
                __half* C = (__half*)Cv;
                *(__half2*)&C[(size_t)r0 * ldc + c0]       = __floats2half2_rn(x0, y0);
                *(__half2*)&C[(size_t)(r0 + 8) * ldc + c0] = __floats2half2_rn(x1, y1);
            } else {
                float* C = (float*)Cv;
                *(float2*)&C[(size_t)r0 * ldc + c0]       = make_float2(x0, y0);
                *(float2*)&C[(size_t)(r0 + 8) * ldc + c0] = make_float2(x1, y1);
            }
        }
    }
}

// Fused QKV projection: blockIdx.z selects {Q,K,V}
__global__ void __launch_bounds__(256) qkv_h(
    const __half* __restrict__ xh,
    const float* __restrict__ bq, const float* __restrict__ bk,
    const float* __restrict__ bv)
{
    const int which = blockIdx.z;
    const __half* W = g_Wh[which];
    const float* bias = (which == 0) ? bq : (which == 1) ? bk : bv;
    __half* C = (which == 0) ? g_Qh : (which == 1) ? g_Kh : g_Vh;
    gemm_nt_f16<true>(xh, Dn, W, Dn, bias, C, Dn, Dn, 1.0f,
                      blockIdx.y * 128, blockIdx.x * 128);
}

// Final projection: out fp32
__global__ void __launch_bounds__(256) proj_f(
    const __half* __restrict__ A, const __half* __restrict__ W,
    const float* __restrict__ bias, float* __restrict__ C)
{
    gemm_nt_f16<false>(A, Dn, W, Dn, bias, C, Dn, Dn, 1.0f,
                       blockIdx.y * 128, blockIdx.x * 128);
}

// ---------------------------------------------------------------------------
// Scores, K=64, MULTI-K-TILE (8 tiles): block keeps Q tile (128 rows) resident
// and processes 8 consecutive 128-col K tiles with double-buffered K prefetch.
// Epilogue stores use __stcs (evict-first): SP is 2x L2 and stream-once.
// smem (dynamic, 82KB): Q 16K | K[2] 32K | staging 34K (stride 272B).
// grid (Sn/1024, Sn/128, Bn*Hn), 256 thr.
// ---------------------------------------------------------------------------
#define SC_SMEM 83968

__global__ void __launch_bounds__(256) scores_k64m()
{
    extern __shared__ __align__(16) char sbuf[];
    uint32_t qsb = smem_u32(sbuf);
    uint32_t ksb[2] = { qsb + 16384, qsb + 32768 };
    char* stage = sbuf + 49152;

    const int zb = blockIdx.z;
    const int b  = zb >> 4;
    const int h  = zb & 15;
    const __half* A = g_Qh + (size_t)b * Sn * Dn + h * HDn;
    const __half* W = g_Kh + (size_t)b * Sn * Dn + h * HDn;
    __half* C = g_SP + (size_t)zb * Sn * Sn;

    const int bm      = blockIdx.y * 128;
    const int bn_base = blockIdx.x * 1024;
    const int tid  = threadIdx.x;
    const int lane = tid & 31;
    const int warp = tid >> 5;
    const int grp  = lane >> 2;
    const int tig  = lane & 3;
    const int wm   = (warp & 3) * 32;
    const int wn   = (warp >> 2) * 64;
    const int lrow = tid >> 1;          // 0..127
    const int lc4  = (tid & 1) * 4;     // chunks 0..3 or 4..7

    // load Q (once) + K tile 0
    {
        const __half* Ag = A + (size_t)(bm + lrow) * Dn;
        const __half* Wg = W + (size_t)(bn_base + lrow) * Dn;
        #pragma unroll
        for (int i = 0; i < 4; ++i) {
            cp16(qsb    + sw128(lrow, lc4 + i), Ag + (lc4 + i) * 8);
            cp16(ksb[0] + sw128(lrow, lc4 + i), Wg + (lc4 + i) * 8);
        }
        cp_commit();
    }

    const int frow = (lane & 7) + ((lane >> 3) & 1) * 8;
    const int fsel = lane >> 4;
    const int ct = tid & 15;        // store: 16B chunk within row
    const int rb = tid >> 4;        // store: base row 0..15

    #pragma unroll
    for (int j = 0; j < 8; ++j) {
        cp_wait0();          // K_j (and Q at j=0) complete
        __syncthreads();

        // prefetch K_{j+1} into the other buffer; overlaps MMA + stores below
        if (j + 1 < 8) {
            const __half* Wg = W + (size_t)(bn_base + (j + 1) * 128 + lrow) * Dn;
            #pragma unroll
            for (int i = 0; i < 4; ++i)
                cp16(ksb[(j + 1) & 1] + sw128(lrow, lc4 + i), Wg + (lc4 + i) * 8);
            cp_commit();
        }

        float acc[2][8][4] = {};
        const uint32_t kb = ksb[j & 1];
        #pragma unroll
        for (int ks = 0; ks < 4; ++ks) {
            const int fch = 2 * ks + fsel;
            uint32_t a[2][4];
            #pragma unroll
            for (int mi = 0; mi < 2; ++mi)
                ldsm4(a[mi][0], a[mi][1], a[mi][2], a[mi][3],
                      qsb + sw128(wm + mi * 16 + frow, fch));
            uint32_t bfr[8][2];
            #pragma unroll
            for (int nj = 0; nj < 4; ++nj) {
                uint32_t r0, r1, r2, r3;
                ldsm4(r0, r1, r2, r3, kb + sw128(wn + nj * 16 + frow, fch));
                bfr[nj * 2][0] = r0;  bfr[nj * 2][1] = r2;
                bfr[nj * 2 + 1][0] = r1;  bfr[nj * 2 + 1][1] = r3;
            }
            #pragma unroll
            for (int mi = 0; mi < 2; ++mi)
                #pragma unroll
                for (int ni = 0; ni < 8; ++ni)
                    mma16816(acc[mi][ni], a[mi][0], a[mi][1], a[mi][2], a[mi][3],
                             bfr[ni][0], bfr[ni][1]);
        }

        // staged epilogue: fragments -> staging (stride 272, conflict-free)
        #pragma unroll
        for (int mi = 0; mi < 2; ++mi) {
            const int r0 = wm + mi * 16 + grp;
            #pragma unroll
            for (int ni = 0; ni < 8; ++ni) {
                const int c0 = wn + ni * 8 + 2 * tig;
                *(__half2*)(stage + (size_t)r0 * 272 + c0 * 2) =
                    __floats2half2_rn(acc[mi][ni][0] * 0.125f, acc[mi][ni][1] * 0.125f);
                *(__half2*)(stage + (size_t)(r0 + 8) * 272 + c0 * 2) =
                    __floats2half2_rn(acc[mi][ni][2] * 0.125f, acc[mi][ni][3] * 0.125f);
            }
        }
        __syncthreads();

        // coalesced store (evict-first): warp covers 2 full 256B rows
        const int bn = bn_base + j * 128;
        #pragma unroll
        for (int i = 0; i < 8; ++i) {
            const int row = rb + 16 * i;
            uint4 v = *(uint4*)(stage + (size_t)row * 272 + ct * 16);
            __stcs((uint4*)&C[(size_t)(bm + row) * Sn + bn + ct * 8], v);
        }
        __syncthreads();   // staging reads done before next iter's stage writes
    }
}

// ---------------------------------------------------------------------------
// Softmax over HEAD axis (axis=1, faithful), IN PLACE, 4 k-positions/thread.
// Streaming cache hints: __ldcs / __stcs (SP buffer is stream-once, 2x L2).
// ---------------------------------------------------------------------------
__global__ void __launch_bounds__(256) softmax_h16()
{
    const size_t SS = (size_t)Sn * Sn;
    const size_t idx = (size_t)blockIdx.x * 256 + threadIdx.x;   // < Bn*SS/4
    const size_t b    = idx / (SS / 4);
    const size_t rem4 = idx % (SS / 4);
    __half* base = g_SP + b * Hn * SS + rem4 * 4;

    float v[Hn][4];
    float mx[4] = {-1e30f, -1e30f, -1e30f, -1e30f};
    #pragma unroll
    for (int h = 0; h < Hn; ++h) {
        uint2 u = __ldcs((const uint2*)&base[(size_t)h * SS]);
        float2 p0 = __half22float2(*(__half2*)&u.x);
        float2 p1 = __half22float2(*(__half2*)&u.y);
        v[h][0] = p0.x; v[h][1] = p0.y; v[h][2] = p1.x; v[h][3] = p1.y;
        mx[0] = fmaxf(mx[0], p0.x); mx[1] = fmaxf(mx[1], p0.y);
        mx[2] = fmaxf(mx[2], p1.x); mx[3] = fmaxf(mx[3], p1.y);
    }
    float sum[4] = {0.f, 0.f, 0.f, 0.f};
    #pragma unroll
    for (int h = 0; h < Hn; ++h) {
        #pragma unroll
        for (int j = 0; j < 4; ++j) {
            v[h][j] = __expf(v[h][j] - mx[j]);
            sum[j] += v[h][j];
        }
    }
    float inv[4] = {1.f / sum[0], 1.f / sum[1], 1.f / sum[2], 1.f / sum[3]};
    #pragma unroll
    for (int h = 0; h < Hn; ++h) {
        __half2 h0 = __floats2half2_rn(v[h][0] * inv[0], v[h][1] * inv[1]);
        __half2 h1 = __floats2half2_rn(v[h][2] * inv[2], v[h][3] * inv[3]);
        uint2 u;
        u.x = *(uint32_t*)&h0;
        u.y = *(uint32_t*)&h1;
        __stcs((uint2*)&base[(size_t)h * SS], u);
    }
}

// ---------------------------------------------------------------------------
// Transpose Vh[b*S + tok][d] -> Vt[b][d][tok] (fp16), 64x64 tiles
// ---------------------------------------------------------------------------
__global__ void __launch_bounds__(256) transpose_v()
{
    __shared__ __half ts[64][72];
    const int t0 = blockIdx.x * 64;
    const int d0 = blockIdx.y * 64;
    const int b  = blockIdx.z;
    const int tid = threadIdx.x;

    const __half* src = g_Vh + ((size_t)b * Sn + t0) * Dn + d0;
    const int r = tid >> 2, c2 = (tid & 3) * 2;
    *(uint4*)&ts[r][c2 * 8]     = *(const uint4*)(src + (size_t)r * Dn + c2 * 8);
    *(uint4*)&ts[r][c2 * 8 + 8] = *(const uint4*)(src + (size_t)r * Dn + c2 * 8 + 8);
    __syncthreads();

    const int dl = tid >> 2, seg = tid & 3;
    __half tmp[16];
    #pragma unroll
    for (int j = 0; j < 16; ++j) tmp[j] = ts[seg * 16 + j][dl];
    __half* dst = g_Vt + ((size_t)b * Dn + d0 + dl) * Sn + t0 + seg * 16;
    *(uint4*)dst       = *(uint4*)tmp;
    *(uint4*)(dst + 8) = *(uint4*)(tmp + 8);
}

// ---------------------------------------------------------------------------
// AV, 256q blocks (512 thr, 16 warps on m), BK=32 2-stage:
// per (b,h): O[q,d] = sum_k P_h[q,k] * Vt_h[d,k].
// smem: 2 x (16KB P + 4KB V) = 40KB. grid (S/256, 1, B*H) = 256 blocks.
// ---------------------------------------------------------------------------
__global__ void __launch_bounds__(512) av_h2()
{
    __shared__ __align__(16) char Ps[2][16384];   // 256 rows x 64 B
    __shared__ __align__(16) char Vs[2][4096];    // 64 rows x 64 B

    const int zb = blockIdx.z;
    const int b  = zb >> 4;
    const int h  = zb & 15;
    const __half* P  = g_SP + (size_t)zb * Sn * Sn;
    const __half* Vt = g_Vt + ((size_t)b * Dn + h * HDn) * Sn;
    __half* C = g_AOh + (size_t)b * Sn * Dn + h * HDn;

    const int tid  = threadIdx.x;
    const int lane = tid & 31;
    const int warp = tid >> 5;          // 0..15
    const int grp  = lane >> 2;
    const int tig  = lane & 3;
    const int bm   = blockIdx.x * 256;
    const int wm   = warp * 16;         // 0..240
    const int prow = tid >> 1;          // 0..255
    const int pc2  = (tid & 1) * 2;     // chunks 0-1 or 2-3
    const int vrow = (tid & 255) >> 2;  // 0..63
    const int vc   = tid & 3;           // 0..3
    const bool vldr = tid < 256;

    uint32_t psb[2] = { smem_u32(Ps[0]), smem_u32(Ps[1]) };
    uint32_t vsb[2] = { smem_u32(Vs[0]), smem_u32(Vs[1]) };

    const __half* Pg = P  + (size_t)(bm + prow) * Sn;
    const __half* Vg = Vt + (size_t)vrow * Sn;

    float acc[8][4] = {};

    cp16(psb[0] + sw_off(prow, pc2),     Pg + pc2 * 8);
    cp16(psb[0] + sw_off(prow, pc2 + 1), Pg + pc2 * 8 + 8);
    if (vldr) cp16(vsb[0] + sw_off(vrow, vc), Vg + vc * 8);
    cp_commit();

    const int nIter = Sn >> 5;   // 64
    for (int it = 0; it < nIter; ++it) {
        const int buf = it & 1;
        cp_wait0();
        __syncthreads();
        if (it + 1 < nIter) {
            const int k0 = (it + 1) << 5;
            cp16(psb[buf ^ 1] + sw_off(prow, pc2),     Pg + k0 + pc2 * 8);
            cp16(psb[buf ^ 1] + sw_off(prow, pc2 + 1), Pg + k0 + pc2 * 8 + 8);
            if (vldr) cp16(vsb[buf ^ 1] + sw_off(vrow, vc), Vg + k0 + vc * 8);
            cp_commit();
        }
        #pragma unroll
        for (int ks = 0; ks < 2; ++ks) {
            const int frow = (lane & 7) + ((lane >> 3) & 1) * 8;
            const int fch  = ks * 2 + (lane >> 4);
            uint32_t a[4];
            ldsm4(a[0], a[1], a[2], a[3], psb[buf] + sw_off(wm + frow, fch));
            uint32_t bfr[8][2];
            #pragma unroll
            for (int nj = 0; nj < 4; ++nj) {
                uint32_t r0, r1, r2, r3;
                ldsm4(r0, r1, r2, r3, vsb[buf] + sw_off(nj * 16 + frow, fch));
                bfr[nj * 2][0] = r0;  bfr[nj * 2][1] = r2;
                bfr[nj * 2 + 1][0] = r1;  bfr[nj * 2 + 1][1] = r3;
            }
            #pragma unroll
            for (int ni = 0; ni < 8; ++ni)
                mma16816(acc[ni], a[0], a[1], a[2], a[3], bfr[ni][0], bfr[ni][1]);
        }
    }

    const int r0 = bm + wm + grp;
    #pragma unroll
    for (int ni = 0; ni < 8; ++ni) {
        const int c0 = ni * 8 + 2 * tig;
        *(__half2*)&C[(size_t)r0 * Dn + c0]       = __floats2half2_rn(acc[ni][0], acc[ni][1]);
        *(__half2*)&C[(size_t)(r0 + 8) * Dn + c0] = __floats2half2_rn(acc[ni][2], acc[ni][3]);
    }
}

// ---------------------------------------------------------------------------
// One-shot fp32 -> fp16 conversion of x + 4 weight matrices.
// ---------------------------------------------------------------------------
__global__ void __launch_bounds__(256) conv_all(
    const float* __restrict__ x,
    const float* __restrict__ Wq, const float* __restrict__ Wk,
    const float* __restrict__ Wv, const float* __restrict__ Wo)
{
    const size_t t = (size_t)blockIdx.x * 256 + threadIdx.x;
    const float* s;
    __half* d;
    size_t off;
    if (t < 524288)      { s = x;  d = g_xh;    off = t; }
    else if (t < 655360) { s = Wq; d = g_Wh[0]; off = t - 524288; }
    else if (t < 786432) { s = Wk; d = g_Wh[1]; off = t - 655360; }
    else if (t < 917504) { s = Wv; d = g_Wh[2]; off = t - 786432; }
    else                 { s = Wo; d = g_Wh[3]; off = t - 917504; }
    const size_t i = off * 8;
    float4 a = *(const float4*)(s + i);
    float4 b = *(const float4*)(s + i + 4);
    __half2 h0 = __floats2half2_rn(a.x, a.y), h1 = __floats2half2_rn(a.z, a.w);
    __half2 h2 = __floats2half2_rn(b.x, b.y), h3 = __floats2half2_rn(b.z, b.w);
    uint4 o;
    o.x = *(uint32_t*)&h0; o.y = *(uint32_t*)&h1;
    o.z = *(uint32_t*)&h2; o.w = *(uint32_t*)&h3;
    *(uint4*)(d + i) = o;
}

// ---------------------------------------------------------------------------
extern "C" void kernel_launch(void* const* d_in, const int* in_sizes, int n_in,
                              void* d_out, int out_size)
{
    const float* x  = (const float*)d_in[0];
    const float* Wq = (const float*)d_in[1];
    const float* bq = (const float*)d_in[2];
    const float* Wk = (const float*)d_in[3];
    const float* bk = (const float*)d_in[4];
    const float* Wv = (const float*)d_in[5];
    const float* bv = (const float*)d_in[6];
    const float* Wo = (const float*)d_in[7];
    const float* bo = (const float*)d_in[8];
    float* out = (float*)d_out;

    __half *xh, *Wh, *AOh;
    cudaGetSymbolAddress((void**)&xh,  g_xh);
    cudaGetSymbolAddress((void**)&Wh,  g_Wh);
    cudaGetSymbolAddress((void**)&AOh, g_AOh);

    const size_t WN = (size_t)Dn * Dn;

    // launch 0: all conversions
    conv_all<<<4096, 256>>>(x, Wq, Wk, Wv, Wo);

    // launch 1: fused QKV projections (2-stage core)
    dim3 gqkv(Dn / 128, Mn / 128, 3);
    qkv_h<<<gqkv, 256>>>(xh, bq, bk, bv);

    // launch 2: V transpose
    dim3 gtr(Sn / 64, Dn / 64, Bn);
    transpose_v<<<gtr, 256>>>();

    // launch 3: scores, K=64 multi-k-tile (8 tiles), staged epilogue (fp16 out)
    cudaFuncSetAttribute(scores_k64m,
                         cudaFuncAttributeMaxDynamicSharedMemorySize, SC_SMEM);
    dim3 gs(Sn / 1024, Sn / 128, Bn * Hn);
    scores_k64m<<<gs, 256, SC_SMEM>>>();

    // launch 4: softmax over head axis, in place (4 positions/thread, ldcs/stcs)
    const size_t tot4 = (size_t)Bn * Sn * Sn / 4;
    softmax_h16<<<(unsigned)(tot4 / 256), 256>>>();

    // launch 5: attn @ V (256q blocks, 512 thr, BK=32 2-stage)
    dim3 gav(Sn / 256, 1, Bn * Hn);
    av_h2<<<gav, 512>>>();

    // launch 6: output projection (2-stage core)
    dim3 gproj(Dn / 128, Mn / 128);
    proj_f<<<gproj, 256>>>(AOh, Wh + 3 * WN, bo, out);
}